// round 13
// baseline (speedup 1.0000x reference)
#include <cuda_runtime.h>

// LRF_11330123727115
// Inputs : d_in[0] = neighbor (B=64, G=2048, S=64, C=3) float32 (center unused)
// Output : d_out = [ rot_neighbor (B,G,S,3) | lrfs (B,G,3,3) ] float32
//
// R13: warp-independent (no smem/barriers), GPW=16, HALF-WARP PAIRING:
// groups are processed two at a time — lanes 0-15 own group 2t, lanes 16-31
// own group 2t+1, 4 points per lane. Butterfly reductions take 4 steps (not 5)
// and each reduction instruction serves TWO groups, halving the per-group
// SHFL/ballot issue cost that bound R12 (issue=68.3%, alu=35.8%).
// Eigensolver (lanes 0-15; 16-31 get the zero matrix fast path) is the
// register-resident LAPACK-faithful fp32 ssytd2+ssteqr+sormtr — signs match
// jnp.linalg.eigh (needed for n_pos==32 disambiguation ties, ~9.9%/axis).

constexpr int NG = 64 * 2048;   // 131072 groups
constexpr long long ROT_ELEMS = (long long)NG * 64 * 3;
constexpr int GPW = 16;         // groups per warp (8 pairs)

// ---------------- LAPACK helper emulations (fp32, IEEE ops) ----------------

__device__ __forceinline__ float f_slapy2(float x, float y) {
    float ax = fabsf(x), ay = fabsf(y);
    float w = fmaxf(ax, ay), z = fminf(ax, ay);
    if (z == 0.f) return w;
    float q = __fdiv_rn(z, w);
    return w * __fsqrt_rn(1.f + q * q);
}

// LAPACK >= 3.10 slartg: r = sign(f)*sqrt(f^2+g^2), c = |f|/|r| >= 0, s = g/r
__device__ __forceinline__ void f_slartg(float f, float g, float& c, float& s, float& r) {
    if (g == 0.f)      { c = 1.f; s = 0.f; r = f; }
    else if (f == 0.f) { c = 0.f; s = copysignf(1.f, g); r = fabsf(g); }
    else {
        float d = __fsqrt_rn(f * f + g * g);
        c = __fdiv_rn(fabsf(f), d);
        r = copysignf(d, f);
        s = __fdiv_rn(g, r);
    }
}

__device__ __forceinline__ void f_slaev2(float a, float b, float c,
                                         float& rt1, float& rt2,
                                         float& cs1, float& sn1) {
    float sm = a + c, df = a - c;
    float adf = fabsf(df), tb = b + b, ab = fabsf(tb);
    float acmx, acmn;
    if (fabsf(a) > fabsf(c)) { acmx = a; acmn = c; } else { acmx = c; acmn = a; }
    float rt;
    if (adf > ab)      { float q = __fdiv_rn(ab, adf); rt = adf * __fsqrt_rn(1.f + q * q); }
    else if (adf < ab) { float q = __fdiv_rn(adf, ab); rt = ab * __fsqrt_rn(1.f + q * q); }
    else               rt = ab * __fsqrt_rn(2.f);
    int sgn1;
    if (sm < 0.f) {
        rt1 = 0.5f * (sm - rt); sgn1 = -1;
        rt2 = __fdiv_rn(acmx, rt1) * acmn - __fdiv_rn(b, rt1) * b;
    } else if (sm > 0.f) {
        rt1 = 0.5f * (sm + rt); sgn1 = 1;
        rt2 = __fdiv_rn(acmx, rt1) * acmn - __fdiv_rn(b, rt1) * b;
    } else {
        rt1 = 0.5f * rt; rt2 = -0.5f * rt; sgn1 = 1;
    }
    int sgn2; float cs;
    if (df >= 0.f) { cs = df + rt; sgn2 = 1; }
    else           { cs = df - rt; sgn2 = -1; }
    float acs = fabsf(cs);
    if (acs > ab) {
        float ct = __fdiv_rn(-tb, cs);
        sn1 = __fdiv_rn(1.f, __fsqrt_rn(1.f + ct * ct));
        cs1 = ct * sn1;
    } else if (ab == 0.f) {
        cs1 = 1.f; sn1 = 0.f;
    } else {
        float tn = __fdiv_rn(-cs, tb);
        cs1 = __fdiv_rn(1.f, __fsqrt_rn(1.f + tn * tn));
        sn1 = tn * cs1;
    }
    if (sgn1 == sgn2) { float tn = cs1; cs1 = -sn1; sn1 = tn; }
}

// ssyevd(n=3, uplo='L') emulation: ssytd2 -> ssteqr('I') -> sort -> sormtr.
// Fully register-resident. FP op sequence identical to R5..R12.
__device__ void eigh3_lapack(float a11, float a21, float a31,
                             float a22, float a32, float a33,
                             float& zvx, float& zvy, float& zvz,
                             float& xvx, float& xvy, float& xvz) {
    // ---- ssytd2 lower: one reflector annihilating a31 ----
    float d0, d1, d2, e0, e1, tau1, v3;
    {
        float xnorm = fabsf(a31);
        if (xnorm == 0.f) { tau1 = 0.f; v3 = 0.f; e0 = a21; }
        else {
            float beta = -copysignf(f_slapy2(a21, xnorm), a21);
            tau1 = __fdiv_rn(beta - a21, beta);
            v3 = a31 * __fdiv_rn(1.f, a21 - beta);
            e0 = beta;
        }
        if (tau1 != 0.f) {
            float x1 = tau1 * (a22 + a32 * v3);   // x = tau*A22*v, v=[1,v3]
            float x2 = tau1 * (a32 + a33 * v3);
            float al = -0.5f * tau1 * (x1 + x2 * v3);
            float w1 = x1 + al;
            float w2 = x2 + al * v3;
            a22 = a22 - w1 - w1;                  // A -= v w^T + w v^T
            a32 = a32 - v3 * w1 - w2;
            a33 = a33 - v3 * w2 - v3 * w2;
        }
        d0 = a11; d1 = a22; d2 = a33; e1 = a32;
    }

    // Z kept as 9 registers, z<row><col>
    float z00 = 1.f, z01 = 0.f, z02 = 0.f;
    float z10 = 0.f, z11 = 1.f, z12 = 0.f;
    float z20 = 0.f, z21 = 0.f, z22 = 1.f;

    auto dget = [&](int i) -> float { return i == 0 ? d0 : (i == 1 ? d1 : d2); };
    auto dset = [&](int i, float v) { if (i == 0) d0 = v; else if (i == 1) d1 = v; else d2 = v; };
    auto eget = [&](int i) -> float { return i == 0 ? e0 : e1; };
    auto eset = [&](int i, float v) { if (i == 0) e0 = v; else e1 = v; };
    auto zrot = [&](int lo, float cc, float ss) {
        float t;
        if (lo == 0) {
            t = z01; z01 = cc * t - ss * z00; z00 = ss * t + cc * z00;
            t = z11; z11 = cc * t - ss * z10; z10 = ss * t + cc * z10;
            t = z21; z21 = cc * t - ss * z20; z20 = ss * t + cc * z20;
        } else {
            t = z02; z02 = cc * t - ss * z01; z01 = ss * t + cc * z01;
            t = z12; z12 = cc * t - ss * z11; z11 = ss * t + cc * z11;
            t = z22; z22 = cc * t - ss * z21; z21 = ss * t + cc * z21;
        }
    };
    auto zswap = [&](int a, int b) {   // swap columns a<b
        float t;
        if (a == 0 && b == 1) {
            t = z00; z00 = z01; z01 = t;
            t = z10; z10 = z11; z11 = t;
            t = z20; z20 = z21; z21 = t;
        } else if (a == 0 && b == 2) {
            t = z00; z00 = z02; z02 = t;
            t = z10; z10 = z12; z12 = t;
            t = z20; z20 = z22; z22 = t;
        } else {
            t = z01; z01 = z02; z02 = t;
            t = z11; z11 = z12; z12 = t;
            t = z21; z21 = z22; z22 = t;
        }
    };

    // ---- ssteqr('I', n=3) ----
    const float eps    = 5.9604645e-08f;   // slamch('E') for IEEE single
    const float eps2   = eps * eps;
    const float safmin = 1.1754944e-38f;
    const int   nmaxit = 90;               // 3 * 30
    int jtot = 0, l1 = 1;
    float wc0 = 0.f, wc1 = 0.f, ws0 = 0.f, ws1 = 0.f;
    auto wcget = [&](int i) -> float { return i == 0 ? wc0 : wc1; };
    auto wsget = [&](int i) -> float { return i == 0 ? ws0 : ws1; };
    auto wcset = [&](int i, float v) { if (i == 0) wc0 = v; else wc1 = v; };
    auto wsset = [&](int i, float v) { if (i == 0) ws0 = v; else ws1 = v; };

    for (;;) {                                       // label 10
        if (l1 > 3) break;
        if (l1 > 1) eset(l1 - 2, 0.f);
        int m = 3;
        if (l1 <= 2) {
            for (int mm = l1; mm <= 2; mm++) {
                float tst = fabsf(eget(mm - 1));
                if (tst == 0.f) { m = mm; break; }
                if (tst <= (__fsqrt_rn(fabsf(dget(mm - 1))) *
                            __fsqrt_rn(fabsf(dget(mm)))) * eps) {
                    eset(mm - 1, 0.f); m = mm; break;
                }
            }
        }
        int l = l1, lsv = l, lend = m, lendsv = lend;
        l1 = m + 1;
        if (lend == l) continue;
        float anorm = 0.f;
        for (int i = l; i <= lend; i++)     anorm = fmaxf(anorm, fabsf(dget(i - 1)));
        for (int i = l; i <= lend - 1; i++) anorm = fmaxf(anorm, fabsf(eget(i - 1)));
        if (anorm == 0.f) continue;
        if (fabsf(dget(lend - 1)) < fabsf(dget(l - 1))) { lend = lsv; l = lendsv; }

        if (lend > l) {
            // ================= QL iteration =================
            for (;;) {                                // label 40
                int m2 = lend;
                if (l != lend) {
                    for (int mm = l; mm <= lend - 1; mm++) {
                        float ev = eget(mm - 1);
                        float tst = ev * ev;
                        if (tst <= (eps2 * fabsf(dget(mm - 1))) * fabsf(dget(mm)) + safmin) {
                            m2 = mm; break;
                        }
                    }
                }
                if (m2 < lend) eset(m2 - 1, 0.f);
                float p = dget(l - 1);
                if (m2 == l) {                        // eigenvalue found
                    dset(l - 1, p); l++;
                    if (l <= lend) continue;
                    break;
                }
                if (m2 == l + 1) {                    // 2x2 deflation
                    float rt1, rt2, c2, s2;
                    f_slaev2(dget(l - 1), eget(l - 1), dget(l), rt1, rt2, c2, s2);
                    zrot(l - 1, c2, s2);
                    dset(l - 1, rt1); dset(l, rt2); eset(l - 1, 0.f);
                    l += 2;
                    if (l <= lend) continue;
                    break;
                }
                if (jtot == nmaxit) break;
                jtot++;
                float g = __fdiv_rn(dget(l) - p, 2.f * eget(l - 1));
                float r = f_slapy2(g, 1.f);
                g = dget(m2 - 1) - p + __fdiv_rn(eget(l - 1), g + copysignf(r, g));
                float sv = 1.f, cv = 1.f;
                p = 0.f;
                for (int i = m2 - 1; i >= l; i--) {
                    float f = sv * eget(i - 1);
                    float b = cv * eget(i - 1);
                    f_slartg(g, f, cv, sv, r);
                    if (i != m2 - 1) eset(i, r);
                    g = dget(i) - p;
                    r = (dget(i - 1) - g) * sv + 2.f * cv * b;
                    p = sv * r;
                    dset(i, g + p);
                    g = cv * r - b;
                    wcset(i - 1, cv); wsset(i - 1, -sv);
                }
                int mm = m2 - l + 1;                  // slasr 'R','V','B'
                for (int j = mm - 1; j >= 1; j--) {
                    float cc = wcget(l + j - 2), ssv = wsget(l + j - 2);
                    zrot(l + j - 2, cc, ssv);
                }
                dset(l - 1, dget(l - 1) - p);
                eset(l - 1, g);
            }
        } else {
            // ================= QR iteration =================
            for (;;) {                                // label 90
                int m2 = lend;
                if (l != lend) {
                    for (int mm = l; mm >= lend + 1; mm--) {
                        float ev = eget(mm - 2);
                        float tst = ev * ev;
                        if (tst <= (eps2 * fabsf(dget(mm - 1))) * fabsf(dget(mm - 2)) + safmin) {
                            m2 = mm; break;
                        }
                    }
                }
                if (m2 > lend) eset(m2 - 2, 0.f);
                float p = dget(l - 1);
                if (m2 == l) {
                    dset(l - 1, p); l--;
                    if (l >= lend) continue;
                    break;
                }
                if (m2 == l - 1) {
                    float rt1, rt2, c2, s2;
                    f_slaev2(dget(l - 2), eget(l - 2), dget(l - 1), rt1, rt2, c2, s2);
                    zrot(l - 2, c2, s2);
                    dset(l - 2, rt1); dset(l - 1, rt2); eset(l - 2, 0.f);
                    l -= 2;
                    if (l >= lend) continue;
                    break;
                }
                if (jtot == nmaxit) break;
                jtot++;
                float g = __fdiv_rn(dget(l - 2) - p, 2.f * eget(l - 2));
                float r = f_slapy2(g, 1.f);
                g = dget(m2 - 1) - p + __fdiv_rn(eget(l - 2), g + copysignf(r, g));
                float sv = 1.f, cv = 1.f;
                p = 0.f;
                for (int i = m2; i <= l - 1; i++) {
                    float f = sv * eget(i - 1);
                    float b = cv * eget(i - 1);
                    f_slartg(g, f, cv, sv, r);
                    if (i != m2) eset(i - 2, r);
                    g = dget(i - 1) - p;
                    r = (dget(i) - g) * sv + 2.f * cv * b;
                    p = sv * r;
                    dset(i - 1, g + p);
                    g = cv * r - b;
                    wcset(i - 1, cv); wsset(i - 1, sv);
                }
                int mm = l - m2 + 1;                  // slasr 'R','V','F'
                for (int j = 1; j <= mm - 1; j++) {
                    float cc = wcget(m2 + j - 2), ssv = wsget(m2 + j - 2);
                    zrot(m2 + j - 2, cc, ssv);
                }
                dset(l - 1, dget(l - 1) - p);
                eset(l - 2, g);
            }
        }
    }

    // ---- selection sort ascending (LAPACK convention: min swaps) ----
    #pragma unroll
    for (int ii = 2; ii <= 3; ii++) {
        int i = ii - 1, k = i;
        float p = dget(i - 1);
        for (int j = ii; j <= 3; j++)
            if (dget(j - 1) < p) { k = j; p = dget(j - 1); }
        if (k != i) {
            dset(k - 1, dget(i - 1)); dset(i - 1, p);
            zswap(i - 1, k - 1);
        }
    }

    // ---- sormtr: Z = H1 * Z (H1 acts on rows 1,2) ----
    if (tau1 != 0.f) {
        float t;
        t = z10 + v3 * z20; z10 -= tau1 * t; z20 -= tau1 * v3 * t;
        t = z11 + v3 * z21; z11 -= tau1 * t; z21 -= tau1 * v3 * t;
        t = z12 + v3 * z22; z12 -= tau1 * t; z22 -= tau1 * v3 * t;
    }

    zvx = z00; zvy = z10; zvz = z20;   // smallest eigval
    xvx = z02; xvy = z12; xvz = z22;   // largest eigval
}

// ------------------------------- main kernel -------------------------------
// Warp-independent: warp w handles groups [GPW*w, GPW*w+GPW) in 8 pairs.
// In each pair t: lanes 0-15 own group 2t (4 points/lane), lanes 16-31 own
// group 2t+1. No smem, no barriers.

__global__ __launch_bounds__(256, 5) void lrf_kernel(
    const float* __restrict__ nb, float* __restrict__ out)
{
    const int warp_id = (blockIdx.x * 256 + threadIdx.x) >> 5;
    const int lane    = threadIdx.x & 31;
    const int half    = lane >> 4;        // 0: group 2t, 1: group 2t+1
    const int hl      = lane & 15;        // lane within half
    const int gw      = warp_id * GPW;    // first group of this warp

    // ---------------- phase 1: covariance; lane u (<16) keeps group u's ----
    float c0 = 0.f, c1 = 0.f, c2 = 0.f, c3 = 0.f, c4 = 0.f, c5 = 0.f;

    {
        const float2* sp = (const float2*)(nb + (size_t)(gw + half) * 192);
        float2 D0 = sp[hl * 6 + 0], D1 = sp[hl * 6 + 1], D2 = sp[hl * 6 + 2];
        float2 D3 = sp[hl * 6 + 3], D4 = sp[hl * 6 + 4], D5 = sp[hl * 6 + 5];

        #pragma unroll 1
        for (int t = 0; t < GPW / 2; t++) {
            const float p0x = D0.x, p0y = D0.y, p0z = D1.x;
            const float p1x = D1.y, p1y = D2.x, p1z = D2.y;
            const float p2x = D3.x, p2y = D3.y, p2z = D4.x;
            const float p3x = D4.y, p3y = D5.x, p3z = D5.y;
            // prefetch next pair
            if (t + 1 < GPW / 2) {
                const float2* spn = (const float2*)(nb + (size_t)(gw + 2 * (t + 1) + half) * 192);
                D0 = spn[hl * 6 + 0]; D1 = spn[hl * 6 + 1]; D2 = spn[hl * 6 + 2];
                D3 = spn[hl * 6 + 3]; D4 = spn[hl * 6 + 4]; D5 = spn[hl * 6 + 5];
            }

            // weights: w = (max_norm - norm) / (sum + 1e-6)
            const float n0 = __fsqrt_rn(p0x * p0x + p0y * p0y + p0z * p0z);
            const float n1 = __fsqrt_rn(p1x * p1x + p1y * p1y + p1z * p1z);
            const float n2 = __fsqrt_rn(p2x * p2x + p2y * p2y + p2z * p2z);
            const float n3 = __fsqrt_rn(p3x * p3x + p3y * p3y + p3z * p3z);
            float mx = fmaxf(fmaxf(n0, n1), fmaxf(n2, n3));
            #pragma unroll
            for (int dd = 8; dd; dd >>= 1)
                mx = fmaxf(mx, __shfl_xor_sync(0xffffffffu, mx, dd));
            const float w0 = mx - n0, w1 = mx - n1, w2 = mx - n2, w3 = mx - n3;
            float swt = (w0 + w1) + (w2 + w3);
            #pragma unroll
            for (int dd = 8; dd; dd >>= 1)
                swt += __shfl_xor_sync(0xffffffffu, swt, dd);
            const float denom = swt + 1e-6f;
            const float q0 = __fdiv_rn(w0, denom);
            const float q1 = __fdiv_rn(w1, denom);
            const float q2 = __fdiv_rn(w2, denom);
            const float q3 = __fdiv_rn(w3, denom);

            // covariance over scaled_pos = 100*pos, term = (w*sp_k)*sp_l
            const float s0x = 100.f * p0x, s0y = 100.f * p0y, s0z = 100.f * p0z;
            const float s1x = 100.f * p1x, s1y = 100.f * p1y, s1z = 100.f * p1z;
            const float s2x = 100.f * p2x, s2y = 100.f * p2y, s2z = 100.f * p2z;
            const float s3x = 100.f * p3x, s3y = 100.f * p3y, s3z = 100.f * p3z;
            float cxx = ((q0*s0x)*s0x + (q1*s1x)*s1x) + ((q2*s2x)*s2x + (q3*s3x)*s3x);
            float cxy = ((q0*s0y)*s0x + (q1*s1y)*s1x) + ((q2*s2y)*s2x + (q3*s3y)*s3x);
            float cxz = ((q0*s0z)*s0x + (q1*s1z)*s1x) + ((q2*s2z)*s2x + (q3*s3z)*s3x);
            float cyy = ((q0*s0y)*s0y + (q1*s1y)*s1y) + ((q2*s2y)*s2y + (q3*s3y)*s3y);
            float cyz = ((q0*s0z)*s0y + (q1*s1z)*s1y) + ((q2*s2z)*s2y + (q3*s3z)*s3y);
            float czz = ((q0*s0z)*s0z + (q1*s1z)*s1z) + ((q2*s2z)*s2z + (q3*s3z)*s3z);
            #pragma unroll
            for (int dd = 8; dd; dd >>= 1) {
                cxx += __shfl_xor_sync(0xffffffffu, cxx, dd);
                cxy += __shfl_xor_sync(0xffffffffu, cxy, dd);
                cxz += __shfl_xor_sync(0xffffffffu, cxz, dd);
                cyy += __shfl_xor_sync(0xffffffffu, cyy, dd);
                cyz += __shfl_xor_sync(0xffffffffu, cyz, dd);
                czz += __shfl_xor_sync(0xffffffffu, czz, dd);
            }
            // group 2t's cov in lanes 0-15, group 2t+1's in lanes 16-31.
            // hand group 2t+1's to lane 2t+1 via xor-16 exchange.
            const float oxx = __shfl_xor_sync(0xffffffffu, cxx, 16);
            const float oxy = __shfl_xor_sync(0xffffffffu, cxy, 16);
            const float oxz = __shfl_xor_sync(0xffffffffu, cxz, 16);
            const float oyy = __shfl_xor_sync(0xffffffffu, cyy, 16);
            const float oyz = __shfl_xor_sync(0xffffffffu, cyz, 16);
            const float ozz = __shfl_xor_sync(0xffffffffu, czz, 16);
            if (lane == 2 * t) {
                c0 = cxx; c1 = cxy; c2 = cxz; c3 = cyy; c4 = cyz; c5 = czz;
            } else if (lane == 2 * t + 1) {
                c0 = oxx; c1 = oxy; c2 = oxz; c3 = oyy; c4 = oyz; c5 = ozz;
            }
        }
    }

    // ---------------- phase 2: lanes 0..15 solve; rest solve 0 (fast) ------
    float ezx, ezy, ezz, exx, exy, exz;
    eigh3_lapack(c0, c1, c2, c3, c4, c5, ezx, ezy, ezz, exx, exy, exz);

    // ---------------- phase 3: disambiguate + rotate + store ---------------
    {
        const float2* sp = (const float2*)(nb + (size_t)(gw + half) * 192);
        float2 D0 = sp[hl * 6 + 0], D1 = sp[hl * 6 + 1], D2 = sp[hl * 6 + 2];
        float2 D3 = sp[hl * 6 + 3], D4 = sp[hl * 6 + 4], D5 = sp[hl * 6 + 5];

        #pragma unroll 1
        for (int t = 0; t < GPW / 2; t++) {
            const size_t gb = (size_t)(gw + 2 * t + half);
            const float p0x = D0.x, p0y = D0.y, p0z = D1.x;
            const float p1x = D1.y, p1y = D2.x, p1z = D2.y;
            const float p2x = D3.x, p2y = D3.y, p2z = D4.x;
            const float p3x = D4.y, p3y = D5.x, p3z = D5.y;
            if (t + 1 < GPW / 2) {
                const float2* spn = (const float2*)(nb + (size_t)(gw + 2 * (t + 1) + half) * 192);
                D0 = spn[hl * 6 + 0]; D1 = spn[hl * 6 + 1]; D2 = spn[hl * 6 + 2];
                D3 = spn[hl * 6 + 3]; D4 = spn[hl * 6 + 4]; D5 = spn[hl * 6 + 5];
            }

            // broadcast: low half wants lane 2t's vecs, high half lane 2t+1's
            const int src = 2 * t + half;
            float zx = __shfl_sync(0xffffffffu, ezx, src);
            float zy = __shfl_sync(0xffffffffu, ezy, src);
            float zz = __shfl_sync(0xffffffffu, ezz, src);
            float xx = __shfl_sync(0xffffffffu, exx, src);
            float xy = __shfl_sync(0xffffffffu, exy, src);
            float xz = __shfl_sync(0xffffffffu, exz, src);

            // flip if #(pos . v > 0) < 32 per group; tie keeps eigh's sign
            {
                unsigned b0 = __ballot_sync(0xffffffffu, zx*p0x + zy*p0y + zz*p0z > 0.f);
                unsigned b1 = __ballot_sync(0xffffffffu, zx*p1x + zy*p1y + zz*p1z > 0.f);
                unsigned b2 = __ballot_sync(0xffffffffu, zx*p2x + zy*p2y + zz*p2z > 0.f);
                unsigned b3 = __ballot_sync(0xffffffffu, zx*p3x + zy*p3y + zz*p3z > 0.f);
                const unsigned hm = half ? 0xffff0000u : 0x0000ffffu;
                int npos = __popc(b0 & hm) + __popc(b1 & hm) +
                           __popc(b2 & hm) + __popc(b3 & hm);
                if (npos < 32) { zx = -zx; zy = -zy; zz = -zz; }
            }
            {
                unsigned b0 = __ballot_sync(0xffffffffu, xx*p0x + xy*p0y + xz*p0z > 0.f);
                unsigned b1 = __ballot_sync(0xffffffffu, xx*p1x + xy*p1y + xz*p1z > 0.f);
                unsigned b2 = __ballot_sync(0xffffffffu, xx*p2x + xy*p2y + xz*p2z > 0.f);
                unsigned b3 = __ballot_sync(0xffffffffu, xx*p3x + xy*p3y + xz*p3z > 0.f);
                const unsigned hm = half ? 0xffff0000u : 0x0000ffffu;
                int npos = __popc(b0 & hm) + __popc(b1 & hm) +
                           __popc(b2 & hm) + __popc(b3 & hm);
                if (npos < 32) { xx = -xx; xy = -xy; xz = -xz; }
            }

            // y = z x x
            const float yx = zy * xz - zz * xy;
            const float yy = zz * xx - zx * xz;
            const float yz = zx * xy - zy * xx;

            // lrfs: rows = component, cols = (z, y, x); lane 0 / lane 16
            if (hl == 0) {
                float* L = out + ROT_ELEMS + gb * 9;
                L[0] = zx; L[1] = yx; L[2] = xx;
                L[3] = zy; L[4] = yy; L[5] = xy;
                L[6] = zz; L[7] = yz; L[8] = xz;
            }

            // rot_neighbor = pos @ lrfs : per point (dot z, dot y, dot x)
            const float r0z = p0x*zx + p0y*zy + p0z*zz;
            const float r0y = p0x*yx + p0y*yy + p0z*yz;
            const float r0x = p0x*xx + p0y*xy + p0z*xz;
            const float r1z = p1x*zx + p1y*zy + p1z*zz;
            const float r1y = p1x*yx + p1y*yy + p1z*yz;
            const float r1x = p1x*xx + p1y*xy + p1z*xz;
            const float r2z = p2x*zx + p2y*zy + p2z*zz;
            const float r2y = p2x*yx + p2y*yy + p2z*yz;
            const float r2x = p2x*xx + p2y*xy + p2z*xz;
            const float r3z = p3x*zx + p3y*zy + p3z*zz;
            const float r3y = p3x*yx + p3y*yy + p3z*yz;
            const float r3x = p3x*xx + p3y*xy + p3z*xz;

            float2* dp = (float2*)(out + gb * 192);
            dp[hl * 6 + 0] = make_float2(r0z, r0y);
            dp[hl * 6 + 1] = make_float2(r0x, r1z);
            dp[hl * 6 + 2] = make_float2(r1y, r1x);
            dp[hl * 6 + 3] = make_float2(r2z, r2y);
            dp[hl * 6 + 4] = make_float2(r2x, r3z);
            dp[hl * 6 + 5] = make_float2(r3y, r3x);
        }
    }
}

extern "C" void kernel_launch(void* const* d_in, const int* in_sizes, int n_in,
                              void* d_out, int out_size) {
    const float* neighbor = (const float*)d_in[0];
    float* out = (float*)d_out;
    // 8 independent warps per block; each warp handles GPW groups (8 pairs)
    lrf_kernel<<<NG / (8 * GPW), 256>>>(neighbor, out);
}

// round 14
// speedup vs baseline: 1.2604x; 1.2604x over previous
#include <cuda_runtime.h>

// LRF_11330123727115
// Inputs : d_in[0] = neighbor (B=64, G=2048, S=64, C=3) float32 (center unused)
// Output : d_out = [ rot_neighbor (B,G,S,3) | lrfs (B,G,3,3) ] float32
//
// R14: TWO-KERNEL SPLIT. The solver has a hard parallelism cap (131072 solves
// = 4096 warps = 27.7 warps/SM) and wants 48+ regs; the streaming wants full
// occupancy. One kernel cannot serve both (R11 latency-bound occ 38.6%, R12
// issue-bound 68.3%).
//   Kernel A (grid 512)  : R11 phase1+2 verbatim — covariance + register-
//                          resident LAPACK-faithful fp32 eigensolve; writes
//                          z/x vectors to a 3MB __device__ scratch.
//   Kernel B (grid 16384): 1 warp/group, low regs, ~full occupancy — re-read
//                          points (L2-warm), ballot-disambiguate, rotate,
//                          coalesced stores.
// Eigenvector signs match jnp.linalg.eigh (needed for n_pos==32
// disambiguation ties, ~9.9% per axis). Arithmetic identical to R11.

constexpr int NG = 64 * 2048;   // 131072 groups
constexpr long long ROT_ELEMS = (long long)NG * 64 * 3;
constexpr int GPW = 32;         // groups per warp in kernel A

__device__ float g_vecs[NG * 6];   // per-group z(3), x(3) eigenvectors

// ---------------- LAPACK helper emulations (fp32, IEEE ops) ----------------

__device__ __forceinline__ float f_slapy2(float x, float y) {
    float ax = fabsf(x), ay = fabsf(y);
    float w = fmaxf(ax, ay), z = fminf(ax, ay);
    if (z == 0.f) return w;
    float q = __fdiv_rn(z, w);
    return w * __fsqrt_rn(1.f + q * q);
}

// LAPACK >= 3.10 slartg: r = sign(f)*sqrt(f^2+g^2), c = |f|/|r| >= 0, s = g/r
__device__ __forceinline__ void f_slartg(float f, float g, float& c, float& s, float& r) {
    if (g == 0.f)      { c = 1.f; s = 0.f; r = f; }
    else if (f == 0.f) { c = 0.f; s = copysignf(1.f, g); r = fabsf(g); }
    else {
        float d = __fsqrt_rn(f * f + g * g);
        c = __fdiv_rn(fabsf(f), d);
        r = copysignf(d, f);
        s = __fdiv_rn(g, r);
    }
}

__device__ __forceinline__ void f_slaev2(float a, float b, float c,
                                         float& rt1, float& rt2,
                                         float& cs1, float& sn1) {
    float sm = a + c, df = a - c;
    float adf = fabsf(df), tb = b + b, ab = fabsf(tb);
    float acmx, acmn;
    if (fabsf(a) > fabsf(c)) { acmx = a; acmn = c; } else { acmx = c; acmn = a; }
    float rt;
    if (adf > ab)      { float q = __fdiv_rn(ab, adf); rt = adf * __fsqrt_rn(1.f + q * q); }
    else if (adf < ab) { float q = __fdiv_rn(adf, ab); rt = ab * __fsqrt_rn(1.f + q * q); }
    else               rt = ab * __fsqrt_rn(2.f);
    int sgn1;
    if (sm < 0.f) {
        rt1 = 0.5f * (sm - rt); sgn1 = -1;
        rt2 = __fdiv_rn(acmx, rt1) * acmn - __fdiv_rn(b, rt1) * b;
    } else if (sm > 0.f) {
        rt1 = 0.5f * (sm + rt); sgn1 = 1;
        rt2 = __fdiv_rn(acmx, rt1) * acmn - __fdiv_rn(b, rt1) * b;
    } else {
        rt1 = 0.5f * rt; rt2 = -0.5f * rt; sgn1 = 1;
    }
    int sgn2; float cs;
    if (df >= 0.f) { cs = df + rt; sgn2 = 1; }
    else           { cs = df - rt; sgn2 = -1; }
    float acs = fabsf(cs);
    if (acs > ab) {
        float ct = __fdiv_rn(-tb, cs);
        sn1 = __fdiv_rn(1.f, __fsqrt_rn(1.f + ct * ct));
        cs1 = ct * sn1;
    } else if (ab == 0.f) {
        cs1 = 1.f; sn1 = 0.f;
    } else {
        float tn = __fdiv_rn(-cs, tb);
        cs1 = __fdiv_rn(1.f, __fsqrt_rn(1.f + tn * tn));
        sn1 = tn * cs1;
    }
    if (sgn1 == sgn2) { float tn = cs1; cs1 = -sn1; sn1 = tn; }
}

// ssyevd(n=3, uplo='L') emulation: ssytd2 -> ssteqr('I') -> sort -> sormtr.
// Fully register-resident. FP op sequence identical to R5..R13.
__device__ void eigh3_lapack(float a11, float a21, float a31,
                             float a22, float a32, float a33,
                             float& zvx, float& zvy, float& zvz,
                             float& xvx, float& xvy, float& xvz) {
    // ---- ssytd2 lower: one reflector annihilating a31 ----
    float d0, d1, d2, e0, e1, tau1, v3;
    {
        float xnorm = fabsf(a31);
        if (xnorm == 0.f) { tau1 = 0.f; v3 = 0.f; e0 = a21; }
        else {
            float beta = -copysignf(f_slapy2(a21, xnorm), a21);
            tau1 = __fdiv_rn(beta - a21, beta);
            v3 = a31 * __fdiv_rn(1.f, a21 - beta);
            e0 = beta;
        }
        if (tau1 != 0.f) {
            float x1 = tau1 * (a22 + a32 * v3);   // x = tau*A22*v, v=[1,v3]
            float x2 = tau1 * (a32 + a33 * v3);
            float al = -0.5f * tau1 * (x1 + x2 * v3);
            float w1 = x1 + al;
            float w2 = x2 + al * v3;
            a22 = a22 - w1 - w1;                  // A -= v w^T + w v^T
            a32 = a32 - v3 * w1 - w2;
            a33 = a33 - v3 * w2 - v3 * w2;
        }
        d0 = a11; d1 = a22; d2 = a33; e1 = a32;
    }

    // Z kept as 9 registers, z<row><col>
    float z00 = 1.f, z01 = 0.f, z02 = 0.f;
    float z10 = 0.f, z11 = 1.f, z12 = 0.f;
    float z20 = 0.f, z21 = 0.f, z22 = 1.f;

    auto dget = [&](int i) -> float { return i == 0 ? d0 : (i == 1 ? d1 : d2); };
    auto dset = [&](int i, float v) { if (i == 0) d0 = v; else if (i == 1) d1 = v; else d2 = v; };
    auto eget = [&](int i) -> float { return i == 0 ? e0 : e1; };
    auto eset = [&](int i, float v) { if (i == 0) e0 = v; else e1 = v; };
    auto zrot = [&](int lo, float cc, float ss) {
        float t;
        if (lo == 0) {
            t = z01; z01 = cc * t - ss * z00; z00 = ss * t + cc * z00;
            t = z11; z11 = cc * t - ss * z10; z10 = ss * t + cc * z10;
            t = z21; z21 = cc * t - ss * z20; z20 = ss * t + cc * z20;
        } else {
            t = z02; z02 = cc * t - ss * z01; z01 = ss * t + cc * z01;
            t = z12; z12 = cc * t - ss * z11; z11 = ss * t + cc * z11;
            t = z22; z22 = cc * t - ss * z21; z21 = ss * t + cc * z21;
        }
    };
    auto zswap = [&](int a, int b) {   // swap columns a<b
        float t;
        if (a == 0 && b == 1) {
            t = z00; z00 = z01; z01 = t;
            t = z10; z10 = z11; z11 = t;
            t = z20; z20 = z21; z21 = t;
        } else if (a == 0 && b == 2) {
            t = z00; z00 = z02; z02 = t;
            t = z10; z10 = z12; z12 = t;
            t = z20; z20 = z22; z22 = t;
        } else {
            t = z01; z01 = z02; z02 = t;
            t = z11; z11 = z12; z12 = t;
            t = z21; z21 = z22; z22 = t;
        }
    };

    // ---- ssteqr('I', n=3) ----
    const float eps    = 5.9604645e-08f;   // slamch('E') for IEEE single
    const float eps2   = eps * eps;
    const float safmin = 1.1754944e-38f;
    const int   nmaxit = 90;               // 3 * 30
    int jtot = 0, l1 = 1;
    float wc0 = 0.f, wc1 = 0.f, ws0 = 0.f, ws1 = 0.f;
    auto wcget = [&](int i) -> float { return i == 0 ? wc0 : wc1; };
    auto wsget = [&](int i) -> float { return i == 0 ? ws0 : ws1; };
    auto wcset = [&](int i, float v) { if (i == 0) wc0 = v; else wc1 = v; };
    auto wsset = [&](int i, float v) { if (i == 0) ws0 = v; else ws1 = v; };

    for (;;) {                                       // label 10
        if (l1 > 3) break;
        if (l1 > 1) eset(l1 - 2, 0.f);
        int m = 3;
        if (l1 <= 2) {
            for (int mm = l1; mm <= 2; mm++) {
                float tst = fabsf(eget(mm - 1));
                if (tst == 0.f) { m = mm; break; }
                if (tst <= (__fsqrt_rn(fabsf(dget(mm - 1))) *
                            __fsqrt_rn(fabsf(dget(mm)))) * eps) {
                    eset(mm - 1, 0.f); m = mm; break;
                }
            }
        }
        int l = l1, lsv = l, lend = m, lendsv = lend;
        l1 = m + 1;
        if (lend == l) continue;
        float anorm = 0.f;
        for (int i = l; i <= lend; i++)     anorm = fmaxf(anorm, fabsf(dget(i - 1)));
        for (int i = l; i <= lend - 1; i++) anorm = fmaxf(anorm, fabsf(eget(i - 1)));
        if (anorm == 0.f) continue;
        if (fabsf(dget(lend - 1)) < fabsf(dget(l - 1))) { lend = lsv; l = lendsv; }

        if (lend > l) {
            // ================= QL iteration =================
            for (;;) {                                // label 40
                int m2 = lend;
                if (l != lend) {
                    for (int mm = l; mm <= lend - 1; mm++) {
                        float ev = eget(mm - 1);
                        float tst = ev * ev;
                        if (tst <= (eps2 * fabsf(dget(mm - 1))) * fabsf(dget(mm)) + safmin) {
                            m2 = mm; break;
                        }
                    }
                }
                if (m2 < lend) eset(m2 - 1, 0.f);
                float p = dget(l - 1);
                if (m2 == l) {                        // eigenvalue found
                    dset(l - 1, p); l++;
                    if (l <= lend) continue;
                    break;
                }
                if (m2 == l + 1) {                    // 2x2 deflation
                    float rt1, rt2, c2, s2;
                    f_slaev2(dget(l - 1), eget(l - 1), dget(l), rt1, rt2, c2, s2);
                    zrot(l - 1, c2, s2);
                    dset(l - 1, rt1); dset(l, rt2); eset(l - 1, 0.f);
                    l += 2;
                    if (l <= lend) continue;
                    break;
                }
                if (jtot == nmaxit) break;
                jtot++;
                float g = __fdiv_rn(dget(l) - p, 2.f * eget(l - 1));
                float r = f_slapy2(g, 1.f);
                g = dget(m2 - 1) - p + __fdiv_rn(eget(l - 1), g + copysignf(r, g));
                float sv = 1.f, cv = 1.f;
                p = 0.f;
                for (int i = m2 - 1; i >= l; i--) {
                    float f = sv * eget(i - 1);
                    float b = cv * eget(i - 1);
                    f_slartg(g, f, cv, sv, r);
                    if (i != m2 - 1) eset(i, r);
                    g = dget(i) - p;
                    r = (dget(i - 1) - g) * sv + 2.f * cv * b;
                    p = sv * r;
                    dset(i, g + p);
                    g = cv * r - b;
                    wcset(i - 1, cv); wsset(i - 1, -sv);
                }
                int mm = m2 - l + 1;                  // slasr 'R','V','B'
                for (int j = mm - 1; j >= 1; j--) {
                    float cc = wcget(l + j - 2), ssv = wsget(l + j - 2);
                    zrot(l + j - 2, cc, ssv);
                }
                dset(l - 1, dget(l - 1) - p);
                eset(l - 1, g);
            }
        } else {
            // ================= QR iteration =================
            for (;;) {                                // label 90
                int m2 = lend;
                if (l != lend) {
                    for (int mm = l; mm >= lend + 1; mm--) {
                        float ev = eget(mm - 2);
                        float tst = ev * ev;
                        if (tst <= (eps2 * fabsf(dget(mm - 1))) * fabsf(dget(mm - 2)) + safmin) {
                            m2 = mm; break;
                        }
                    }
                }
                if (m2 > lend) eset(m2 - 2, 0.f);
                float p = dget(l - 1);
                if (m2 == l) {
                    dset(l - 1, p); l--;
                    if (l >= lend) continue;
                    break;
                }
                if (m2 == l - 1) {
                    float rt1, rt2, c2, s2;
                    f_slaev2(dget(l - 2), eget(l - 2), dget(l - 1), rt1, rt2, c2, s2);
                    zrot(l - 2, c2, s2);
                    dset(l - 2, rt1); dset(l - 1, rt2); eset(l - 2, 0.f);
                    l -= 2;
                    if (l >= lend) continue;
                    break;
                }
                if (jtot == nmaxit) break;
                jtot++;
                float g = __fdiv_rn(dget(l - 2) - p, 2.f * eget(l - 2));
                float r = f_slapy2(g, 1.f);
                g = dget(m2 - 1) - p + __fdiv_rn(eget(l - 2), g + copysignf(r, g));
                float sv = 1.f, cv = 1.f;
                p = 0.f;
                for (int i = m2; i <= l - 1; i++) {
                    float f = sv * eget(i - 1);
                    float b = cv * eget(i - 1);
                    f_slartg(g, f, cv, sv, r);
                    if (i != m2) eset(i - 2, r);
                    g = dget(i - 1) - p;
                    r = (dget(i) - g) * sv + 2.f * cv * b;
                    p = sv * r;
                    dset(i - 1, g + p);
                    g = cv * r - b;
                    wcset(i - 1, cv); wsset(i - 1, sv);
                }
                int mm = l - m2 + 1;                  // slasr 'R','V','F'
                for (int j = 1; j <= mm - 1; j++) {
                    float cc = wcget(m2 + j - 2), ssv = wsget(m2 + j - 2);
                    zrot(m2 + j - 2, cc, ssv);
                }
                dset(l - 1, dget(l - 1) - p);
                eset(l - 2, g);
            }
        }
    }

    // ---- selection sort ascending (LAPACK convention: min swaps) ----
    #pragma unroll
    for (int ii = 2; ii <= 3; ii++) {
        int i = ii - 1, k = i;
        float p = dget(i - 1);
        for (int j = ii; j <= 3; j++)
            if (dget(j - 1) < p) { k = j; p = dget(j - 1); }
        if (k != i) {
            dset(k - 1, dget(i - 1)); dset(i - 1, p);
            zswap(i - 1, k - 1);
        }
    }

    // ---- sormtr: Z = H1 * Z (H1 acts on rows 1,2) ----
    if (tau1 != 0.f) {
        float t;
        t = z10 + v3 * z20; z10 -= tau1 * t; z20 -= tau1 * v3 * t;
        t = z11 + v3 * z21; z11 -= tau1 * t; z21 -= tau1 * v3 * t;
        t = z12 + v3 * z22; z12 -= tau1 * t; z22 -= tau1 * v3 * t;
    }

    zvx = z00; zvy = z10; zvz = z20;   // smallest eigval
    xvx = z02; xvy = z12; xvz = z22;   // largest eigval
}

// --------------------------- kernel A: cov + solve --------------------------
// Warp-independent: warp w reduces groups [32w, 32w+32); lane u keeps group
// u's covariance; all 32 lanes solve in parallel; writes z/x to g_vecs.

__global__ __launch_bounds__(256, 4) void lrf_cov_solve(
    const float* __restrict__ nb)
{
    const int warp_id = (blockIdx.x * 256 + threadIdx.x) >> 5;
    const int lane    = threadIdx.x & 31;
    const int gw      = warp_id * GPW;

    float c0 = 0.f, c1 = 0.f, c2 = 0.f, c3 = 0.f, c4 = 0.f, c5 = 0.f;

    const float2* sp0 = (const float2*)(nb + (size_t)gw * 192);
    float2 A = sp0[lane * 3 + 0];
    float2 B = sp0[lane * 3 + 1];
    float2 C = sp0[lane * 3 + 2];

    #pragma unroll 1
    for (int u = 0; u < GPW; u++) {
        const float p0x = A.x, p0y = A.y, p0z = B.x;
        const float p1x = B.y, p1y = C.x, p1z = C.y;
        if (u + 1 < GPW) {   // prefetch next group
            const float2* spn = (const float2*)(nb + (size_t)(gw + u + 1) * 192);
            A = spn[lane * 3 + 0];
            B = spn[lane * 3 + 1];
            C = spn[lane * 3 + 2];
        }

        // weights exactly as reference: w = (max_norm - norm) / (sum + 1e-6)
        const float n0 = __fsqrt_rn(p0x * p0x + p0y * p0y + p0z * p0z);
        const float n1 = __fsqrt_rn(p1x * p1x + p1y * p1y + p1z * p1z);
        float mx = fmaxf(n0, n1);
        #pragma unroll
        for (int dd = 16; dd; dd >>= 1)
            mx = fmaxf(mx, __shfl_xor_sync(0xffffffffu, mx, dd));
        const float w0 = mx - n0, w1 = mx - n1;
        float swt = w0 + w1;
        #pragma unroll
        for (int dd = 16; dd; dd >>= 1)
            swt += __shfl_xor_sync(0xffffffffu, swt, dd);
        const float denom = swt + 1e-6f;
        const float q0 = __fdiv_rn(w0, denom);
        const float q1 = __fdiv_rn(w1, denom);

        // covariance over scaled_pos = 100*pos, term = (w*sp_k)*sp_l
        const float s0x = 100.f * p0x, s0y = 100.f * p0y, s0z = 100.f * p0z;
        const float s1x = 100.f * p1x, s1y = 100.f * p1y, s1z = 100.f * p1z;
        float cxx = (q0 * s0x) * s0x + (q1 * s1x) * s1x;
        float cxy = (q0 * s0y) * s0x + (q1 * s1y) * s1x;   // C[1][0]
        float cxz = (q0 * s0z) * s0x + (q1 * s1z) * s1x;   // C[2][0]
        float cyy = (q0 * s0y) * s0y + (q1 * s1y) * s1y;
        float cyz = (q0 * s0z) * s0y + (q1 * s1z) * s1y;   // C[2][1]
        float czz = (q0 * s0z) * s0z + (q1 * s1z) * s1z;
        #pragma unroll
        for (int dd = 16; dd; dd >>= 1) {
            cxx += __shfl_xor_sync(0xffffffffu, cxx, dd);
            cxy += __shfl_xor_sync(0xffffffffu, cxy, dd);
            cxz += __shfl_xor_sync(0xffffffffu, cxz, dd);
            cyy += __shfl_xor_sync(0xffffffffu, cyy, dd);
            cyz += __shfl_xor_sync(0xffffffffu, cyz, dd);
            czz += __shfl_xor_sync(0xffffffffu, czz, dd);
        }
        if (lane == u) { c0 = cxx; c1 = cxy; c2 = cxz; c3 = cyy; c4 = cyz; c5 = czz; }
    }

    // all 32 lanes solve their group in parallel
    float ezx, ezy, ezz, exx, exy, exz;
    eigh3_lapack(c0, c1, c2, c3, c4, c5, ezx, ezy, ezz, exx, exy, exz);

    float* v = g_vecs + (size_t)(gw + lane) * 6;
    v[0] = ezx; v[1] = ezy; v[2] = ezz;
    v[3] = exx; v[4] = exy; v[5] = exz;
}

// ------------------------ kernel B: disambiguate+rotate ---------------------
// One warp per group; low registers, full occupancy, pure streaming.

__global__ __launch_bounds__(256) void lrf_rotate(
    const float* __restrict__ nb, float* __restrict__ out)
{
    const size_t g   = (size_t)(blockIdx.x * 8) + (threadIdx.x >> 5);
    const int lane   = threadIdx.x & 31;

    const float2* sp = (const float2*)(nb + g * 192);
    const float2 A = sp[lane * 3 + 0];
    const float2 B = sp[lane * 3 + 1];
    const float2 C = sp[lane * 3 + 2];
    const float p0x = A.x, p0y = A.y, p0z = B.x;
    const float p1x = B.y, p1y = C.x, p1z = C.y;

    const float* v = g_vecs + g * 6;
    float zx = v[0], zy = v[1], zz = v[2];
    float xx = v[3], xy = v[4], xz = v[5];

    // flip if #(pos . v > 0) < 32 ; tie keeps eigh's sign
    {
        float pj0 = zx * p0x + zy * p0y + zz * p0z;
        float pj1 = zx * p1x + zy * p1y + zz * p1z;
        int npos = __popc(__ballot_sync(0xffffffffu, pj0 > 0.f)) +
                   __popc(__ballot_sync(0xffffffffu, pj1 > 0.f));
        if (npos < 32) { zx = -zx; zy = -zy; zz = -zz; }
    }
    {
        float pj0 = xx * p0x + xy * p0y + xz * p0z;
        float pj1 = xx * p1x + xy * p1y + xz * p1z;
        int npos = __popc(__ballot_sync(0xffffffffu, pj0 > 0.f)) +
                   __popc(__ballot_sync(0xffffffffu, pj1 > 0.f));
        if (npos < 32) { xx = -xx; xy = -xy; xz = -xz; }
    }

    // y = z x x
    const float yx = zy * xz - zz * xy;
    const float yy = zz * xx - zx * xz;
    const float yz = zx * xy - zy * xx;

    // lrfs: rows = component, cols = (z, y, x)
    if (lane == 0) {
        float* L = out + ROT_ELEMS + g * 9;
        L[0] = zx; L[1] = yx; L[2] = xx;
        L[3] = zy; L[4] = yy; L[5] = xy;
        L[6] = zz; L[7] = yz; L[8] = xz;
    }

    // rot_neighbor = pos @ lrfs : per point (dot z, dot y, dot x)
    const float r0z = p0x * zx + p0y * zy + p0z * zz;
    const float r0y = p0x * yx + p0y * yy + p0z * yz;
    const float r0x = p0x * xx + p0y * xy + p0z * xz;
    const float r1z = p1x * zx + p1y * zy + p1z * zz;
    const float r1y = p1x * yx + p1y * yy + p1z * yz;
    const float r1x = p1x * xx + p1y * xy + p1z * xz;

    float2* dp = (float2*)(out + g * 192);
    dp[lane * 3 + 0] = make_float2(r0z, r0y);
    dp[lane * 3 + 1] = make_float2(r0x, r1z);
    dp[lane * 3 + 2] = make_float2(r1y, r1x);
}

extern "C" void kernel_launch(void* const* d_in, const int* in_sizes, int n_in,
                              void* d_out, int out_size) {
    const float* neighbor = (const float*)d_in[0];
    float* out = (float*)d_out;
    // A: 8 warps/block, each warp 32 groups -> 512 blocks
    lrf_cov_solve<<<NG / (8 * GPW), 256>>>(neighbor);
    // B: 8 warps/block, one group per warp -> 16384 blocks
    lrf_rotate<<<NG / 8, 256>>>(neighbor, out);
}